// round 1
// baseline (speedup 1.0000x reference)
#include <cuda_runtime.h>

#define S   512
#define C   192
#define B   2
#define BW  21
#define HALF 10
#define KS  7

// Scratch (allocation-free rule: __device__ globals)
__device__ float g_conv[B * C * S];   // band after depthwise conv
__device__ float g_attn[B * C * S];   // after pointwise + softmax

// ---------------------------------------------------------------------------
// K1: per (b,c) plane — gather diagonal stripe, band mean, depthwise conv k=7
// ---------------------------------------------------------------------------
__global__ void band_conv_kernel(const float* __restrict__ x,
                                 const float* __restrict__ conv_w) {
    __shared__ float stripe[S * BW];   // stripe[r*21 + k] = x[r, r-10+k] (0 OOB)
    __shared__ float band[S];

    const int bc = blockIdx.x;                    // b*C + c
    const int c  = bc % C;
    const int tid = threadIdx.x;                  // 0..511
    const float* plane = x + ((size_t)bc << 18);  // bc * S*S

    // Phase 1: load stripe. Flat index -> contiguous runs of 21 per row,
    // so warps touch few cache lines per transaction.
    for (int idx = tid; idx < S * BW; idx += blockDim.x) {
        const int r = idx / BW;
        const int k = idx - r * BW;
        const int col = r - HALF + k;
        float v = 0.f;
        if (col >= 0 && col < S) v = plane[r * S + col];
        stripe[idx] = v;
    }
    __syncthreads();

    // Phase 2: band[j] = mean over t of x[j-10+t, j] = stripe[(j-10+t)*21 + (20-t)]
    {
        const int j = tid;
        float sum = 0.f;
        #pragma unroll
        for (int t = 0; t < BW; t++) {
            const int r = j - HALF + t;
            if (r >= 0 && r < S) sum += stripe[r * BW + (BW - 1 - t)];
        }
        band[j] = sum * (1.0f / (float)BW);
    }
    __syncthreads();

    // Phase 3: depthwise conv1d, k=7, pad=3 (cross-correlation, per channel)
    {
        const int j = tid;
        float w[KS];
        #pragma unroll
        for (int k = 0; k < KS; k++) w[k] = conv_w[c * KS + k];
        float acc = 0.f;
        #pragma unroll
        for (int k = 0; k < KS; k++) {
            const int s = j + k - 3;
            if (s >= 0 && s < S) acc += band[s] * w[k];
        }
        g_conv[bc * S + j] = acc;
    }
}

// ---------------------------------------------------------------------------
// K2: per (b,d) — pointwise 1x1 conv (GEMV over C) + bias + softmax over S
// ---------------------------------------------------------------------------
__global__ void point_softmax_kernel(const float* __restrict__ point_w,
                                     const float* __restrict__ point_b) {
    __shared__ float wrow[C];
    __shared__ float red[S];

    const int bd = blockIdx.x;         // b*C + d
    const int b  = bd / C;
    const int d  = bd - b * C;
    const int s  = threadIdx.x;        // 0..511

    if (s < C) wrow[s] = point_w[d * C + s];
    __syncthreads();

    const float* cb = g_conv + b * C * S;
    float acc = point_b[d];
    #pragma unroll 4
    for (int c = 0; c < C; c++)
        acc += cb[c * S + s] * wrow[c];

    // softmax over 512 values in the block
    red[s] = acc;
    __syncthreads();
    #pragma unroll
    for (int off = 256; off > 0; off >>= 1) {
        if (s < off) red[s] = fmaxf(red[s], red[s + off]);
        __syncthreads();
    }
    const float m = red[0];
    __syncthreads();

    const float e = __expf(acc - m);
    red[s] = e;
    __syncthreads();
    #pragma unroll
    for (int off = 256; off > 0; off >>= 1) {
        if (s < off) red[s] += red[s + off];
        __syncthreads();
    }
    const float inv = 1.0f / red[0];

    g_attn[bd * S + s] = e * inv;
}

// ---------------------------------------------------------------------------
// K3: streaming float4 copy x -> out, scaling the main diagonal by attn
// ---------------------------------------------------------------------------
__global__ void copy_diag_kernel(const float4* __restrict__ x4,
                                 float4* __restrict__ out4, int n4) {
    const int v = blockIdx.x * blockDim.x + threadIdx.x;
    if (v >= n4) return;

    float4 val = x4[v];

    const int e     = v << 2;          // element index (fits in int: < 2^27)
    const int j0    = e & (S - 1);     // column of lane 0
    const int r     = (e >> 9) & (S - 1);
    const int plane = e >> 18;         // b*C + c
    const int dr    = r - j0;          // diagonal lane within this vector?

    if ((unsigned)dr < 4u) {
        const float a = g_attn[(plane << 9) + r];
        if      (dr == 0) val.x *= a;
        else if (dr == 1) val.y *= a;
        else if (dr == 2) val.z *= a;
        else              val.w *= a;
    }
    out4[v] = val;
}

// ---------------------------------------------------------------------------
extern "C" void kernel_launch(void* const* d_in, const int* in_sizes, int n_in,
                              void* d_out, int out_size) {
    const float* x       = (const float*)d_in[0];   // [2,192,512,512]
    const float* conv_w  = (const float*)d_in[1];   // [192,1,7]
    const float* point_w = (const float*)d_in[2];   // [192,192]
    const float* point_b = (const float*)d_in[3];   // [192]
    float* out = (float*)d_out;

    band_conv_kernel<<<B * C, S>>>(x, conv_w);
    point_softmax_kernel<<<B * C, S>>>(point_w, point_b);

    const int n4 = out_size >> 2;     // 25,165,824 float4 vectors
    const int blocks = (n4 + 255) / 256;
    copy_diag_kernel<<<blocks, 256>>>((const float4*)x, (float4*)out, n4);
}